// round 15
// baseline (speedup 1.0000x reference)
#include <cuda_runtime.h>
#include <cuda_fp16.h>
#include <cstdint>
#include <cstring>

#define FH 38
#define FW 50
#define HW 1900
#define TAPS 15
#define NROIS 512
#define OUTDIM 490
#define S1 5
#define S2 2
#define OCPAD1 256
#define OCPAD2 512
#define PROWS 4096

// ---------------- scratch (zero-initialized at load; pads never written) ----------------
__device__ __half g_XPa[PROWS * 2048];
__device__ __half g_XPb[PROWS * 2048];
__device__ __half g_TP0[PROWS * 256];
__device__ __half g_TP1[PROWS * 256];
__device__ __half g_wt1[2 * TAPS * OCPAD1 * 2048];
__device__ __half g_wt2[2 * TAPS * OCPAD2 * 256];
__device__ float  g_p1[2 * S1 * OCPAD1 * HW];
__device__ float  g_h0[S2 * OCPAD2 * HW];
__device__ float  g_h1[S2 * OCPAD2 * HW];
__device__ float  g_h [HW * 512];
__device__ __half g_flath[NROIS * 512];
__device__ __half g_fc1h [NROIS * 2048];
__device__ __half g_wfc1h[2048 * 512];
__device__ __half g_whh  [512 * 2048];
__device__ float  g_hbias[512];

// ---------------- PTX helpers ----------------
__device__ __forceinline__ uint32_t smem_u32(const void* p) {
    uint32_t a;
    asm("{ .reg .u64 t; cvta.to.shared.u64 t, %1; cvt.u32.u64 %0, t; }" : "=r"(a) : "l"(p));
    return a;
}
__device__ __forceinline__ void cp16(uint32_t dst, const __half* src) {
    asm volatile("cp.async.cg.shared.global [%0], [%1], 16;"
                 :: "r"(dst), "l"(__cvta_generic_to_global(src)));
}
__device__ __forceinline__ void cp_commit() { asm volatile("cp.async.commit_group;" ::: "memory"); }
template<int N> __device__ __forceinline__ void cp_wait() {
    asm volatile("cp.async.wait_group %0;" :: "n"(N) : "memory");
}
__device__ __forceinline__ void ldsm4(uint32_t* r, uint32_t addr) {
    asm volatile("ldmatrix.sync.aligned.m8n8.x4.shared.b16 {%0,%1,%2,%3}, [%4];"
        : "=r"(r[0]), "=r"(r[1]), "=r"(r[2]), "=r"(r[3]) : "r"(addr));
}
__device__ __forceinline__ void mma16(float* c, const uint32_t* a, const uint32_t* b) {
    asm volatile("mma.sync.aligned.m16n8k16.row.col.f32.f16.f16.f32 "
        "{%0,%1,%2,%3}, {%4,%5,%6,%7}, {%8,%9}, {%0,%1,%2,%3};"
        : "+f"(c[0]), "+f"(c[1]), "+f"(c[2]), "+f"(c[3])
        : "r"(a[0]), "r"(a[1]), "r"(a[2]), "r"(a[3]), "r"(b[0]), "r"(b[1]));
}

// ---------------- prep ----------------
__global__ __launch_bounds__(256) void xpose(const float* __restrict__ x,
                                             __half2* __restrict__ XPa, __half2* __restrict__ XPb)
{
    __shared__ float s[64][65];
    const int c0 = blockIdx.x * 64, p0 = blockIdx.y * 64;
    const int tid = threadIdx.x;
    const int r = tid >> 2, q0 = (tid & 3) * 16;
#pragma unroll
    for (int q = 0; q < 16; q++) {
        const int p = p0 + q0 + q;
        s[r][q0 + q] = (p < HW) ? x[(size_t)(c0 + r) * HW + p] : 0.f;
    }
    __syncthreads();
#pragma unroll
    for (int k = 0; k < 8; k++) {
        const int widx = tid + k * 256;
        const int pl = widx >> 5, cp = widx & 31;
        const int p = p0 + pl;
        if (p < HW) {
            const int i = p / FW, j = p - i * FW;
            const __half2 v = __floats2half2_rn(s[2 * cp][pl], s[2 * cp + 1][pl]);
            XPa[(size_t)((i + 7) * 64 + j + 7) * 1024 + (c0 >> 1) + cp] = v;
            XPb[(size_t)((j + 7) * 64 + i + 7) * 1024 + (c0 >> 1) + cp] = v;
        }
    }
}

// w [oc][ic][15] f32 -> wt [t][ocpad][ic] half; vectorized (16B stores)
__global__ __launch_bounds__(256) void wtrans(const float* __restrict__ w0, const float* __restrict__ w1,
                                              __half* __restrict__ wt, size_t dstStride,
                                              int OC, int OCpad, int IC)
{
    __shared__ __align__(16) float s[128 * TAPS];
    const float* w = blockIdx.z ? w1 : w0;
    __half* dst = wt + (size_t)blockIdx.z * dstStride;
    const int m = blockIdx.x, c0 = blockIdx.y * 128;
    const int tid = threadIdx.x;
    if (m < OC) {
        const float4* src4 = (const float4*)(w + ((size_t)m * IC + c0) * TAPS);
        for (int i = tid; i < 128 * TAPS / 4; i += 256) ((float4*)s)[i] = src4[i];
    } else {
        for (int i = tid; i < 128 * TAPS / 4; i += 256)
            ((float4*)s)[i] = make_float4(0.f, 0.f, 0.f, 0.f);
    }
    __syncthreads();
    if (tid < 240) {
        const int t = tid / 16, c8 = (tid & 15) * 8;
        __half2 hv[4];
#pragma unroll
        for (int k = 0; k < 4; k++)
            hv[k] = __floats2half2_rn(s[(c8 + 2 * k) * TAPS + t], s[(c8 + 2 * k + 1) * TAPS + t]);
        *(uint4*)&dst[((size_t)t * OCpad + m) * IC + c0 + c8] = *(uint4*)hv;
    }
}

__global__ void cvt_fc(const float* __restrict__ wfc1,
                       const float* __restrict__ wloc, const float* __restrict__ wsc,
                       const float* __restrict__ bloc, const float* __restrict__ bsc,
                       __half* __restrict__ wfc1h, __half* __restrict__ whh, float* __restrict__ hb)
{
    const int idx = blockIdx.x * blockDim.x + threadIdx.x;
    if (idx < 2048 * 512) {
        const int r = idx >> 9, c = idx & 511;
        wfc1h[idx] = __float2half(c < OUTDIM ? wfc1[(size_t)r * OUTDIM + c] : 0.f);
    }
    if (idx < 512 * 2048) {
        const int r = idx >> 11, k = idx & 2047;
        float v = 0.f;
        if (r < 324) v = wloc[(size_t)r * 2048 + k];
        else if (r < 405) v = wsc[(size_t)(r - 324) * 2048 + k];
        whh[idx] = __float2half(v);
    }
    if (idx < 512) {
        float v = 0.f;
        if (idx < 324) v = bloc[idx];
        else if (idx < 405) v = bsc[idx - 324];
        hb[idx] = v;
    }
}

// ============ sliding-window tap conv: BN=128, 2 CTAs/SM, uneven K-split ============
#define WR 320
#define APITCH 80
#define ABUF (128 * APITCH)
#define BBUF (WR * APITCH)
#define CONV_SMEM (4 * ABUF + 2 * BBUF)    // 92160

__global__ __launch_bounds__(256, 2) void conv_mma(
    const __half* __restrict__ inB0, const __half* __restrict__ inB1,
    const __half* __restrict__ wA0,  const __half* __restrict__ wA1,
    float* __restrict__ out0, float* __restrict__ out1,
    int D0, int D1, int ICfull, int CT, int OCpad, int S)
{
    extern __shared__ __align__(16) char smem[];
    const int z = blockIdx.z;
    const int br = z / S, s = z % S;
    const __half* inB = br ? inB1 : inB0;
    const __half* wA  = br ? wA1  : wA0;
    const int D = br ? D1 : D0;
    float* out = (br ? out1 : out0) + (size_t)s * OCpad * HW;
    const int m0 = blockIdx.y * 128;
    const int pi0 = blockIdx.x * 128;
    const int cs = (s * CT) / S, ce = ((s + 1) * CT) / S;
    const int icChunks = ce - cs;
    const int icOff = cs * 32;
    const int nit = icChunks * TAPS;
    const int row0 = (pi0 / D + 7) * 64 + pi0 % D;

    const int tid = threadIdx.x, lane = tid & 31, wid = tid >> 5;
    const int wm = (wid >> 2) * 64;
    const int wn = (wid & 3) * 32;
    const int lg = lane >> 2, lt = lane & 3;
    const uint32_t sb = smem_u32(smem);
    const uint32_t aB[4] = { sb, sb + ABUF, sb + 2 * ABUF, sb + 3 * ABUF };
    const uint32_t bB[2] = { sb + 4 * ABUF, sb + 4 * ABUF + BBUF };

    const int arow = tid >> 1, aseg = tid & 1;
    const __half* aBase = wA + (size_t)(m0 + arow) * ICfull + icOff + aseg * 16;
    const size_t aTap = (size_t)OCpad * ICfull;
    const uint32_t aDst = (uint32_t)(arow * APITCH + aseg * 32);
    const uint32_t aLane = (uint32_t)((wm + (lane & 7) + ((lane >> 3) & 1) * 8) * APITCH + ((lane >> 4) & 1) * 16);

    uint32_t bLaneOff[2];
#pragma unroll
    for (int pr = 0; pr < 2; pr++) {
        const int nl = wn + (lane & 7) + ((lane >> 4) & 1) * 8 + pr * 16;
        int pi = pi0 + nl; if (pi > HW - 1) pi = HW - 1;
        const int rr = (pi / D + 7) * 64 + pi % D + 7 - row0 - 7;
        bLaneOff[pr] = (uint32_t)(rr * APITCH + ((lane >> 3) & 1) * 16);
    }

    float acc[4][4][4];
#pragma unroll
    for (int mi = 0; mi < 4; mi++)
#pragma unroll
        for (int ni = 0; ni < 4; ni++)
#pragma unroll
            for (int q = 0; q < 4; q++) acc[mi][ni][q] = 0.f;

    auto issueA = [&](int g) {
        const int t = g % TAPS, c = g / TAPS;
        const __half* aS = aBase + (size_t)t * aTap + c * 32;
        const uint32_t d = aB[g & 3] + aDst;
        cp16(d, aS); cp16(d + 16, aS + 8);
    };
    auto issueBwin = [&](int c) {
        const uint32_t bb = bB[c & 1];
        for (int wr = tid; wr < WR; wr += 256) {
            int grow = row0 + wr; if (grow > PROWS - 1) grow = PROWS - 1;
            const __half* src = inB + (size_t)grow * ICfull + icOff + c * 32;
            const uint32_t d = bb + wr * APITCH;
            cp16(d, src); cp16(d + 16, src + 8); cp16(d + 32, src + 16); cp16(d + 48, src + 24);
        }
    };

    issueA(0); issueBwin(0); cp_commit();
    if (nit > 1) issueA(1);
    cp_commit();

    int tCur = 0, cCur = 0;
    for (int g = 0; g < nit; ++g) {
        const int gn = g + 2;
        if (gn < nit) {
            issueA(gn);
            if (gn % TAPS == 0) issueBwin(gn / TAPS);
        }
        cp_commit();
        cp_wait<2>();
        __syncthreads();

        const uint32_t abuf = aB[g & 3];
        const uint32_t bbuf = bB[cCur & 1] + tCur * APITCH;
#pragma unroll
        for (int ks = 0; ks < 2; ks++) {
            uint32_t af[4][4], bf[4][2];
#pragma unroll
            for (int mi = 0; mi < 4; mi++)
                ldsm4(af[mi], abuf + aLane + mi * (16 * APITCH) + ks * 32);
#pragma unroll
            for (int pr = 0; pr < 2; pr++) {
                uint32_t r[4];
                ldsm4(r, bbuf + bLaneOff[pr] + ks * 32);
                bf[pr * 2][0] = r[0]; bf[pr * 2][1] = r[1];
                bf[pr * 2 + 1][0] = r[2]; bf[pr * 2 + 1][1] = r[3];
            }
#pragma unroll
            for (int mi = 0; mi < 4; mi++)
#pragma unroll
                for (int ni = 0; ni < 4; ni++)
                    mma16(acc[mi][ni], af[mi], bf[ni]);
        }
        if (++tCur == TAPS) { tCur = 0; cCur++; }
    }

#pragma unroll
    for (int mi = 0; mi < 4; mi++) {
        const int r0 = m0 + wm + mi * 16 + lg;
#pragma unroll
        for (int ni = 0; ni < 4; ni++) {
            const int cc = pi0 + wn + ni * 8 + 2 * lt;
            if (cc < HW) {
                *(float2*)&out[(size_t)r0 * HW + cc] = make_float2(acc[mi][ni][0], acc[mi][ni][1]);
                *(float2*)&out[(size_t)(r0 + 8) * HW + cc] = make_float2(acc[mi][ni][2], acc[mi][ni][3]);
            }
        }
    }
}

// ============ fp16 GEMM for FC ============
#define GBUF (2 * 128 * APITCH)
#define GEMM_SMEM (3 * GBUF)

__global__ __launch_bounds__(256) void gemm_hmma(
    const __half* __restrict__ A, const __half* __restrict__ B, const float* __restrict__ bias,
    __half* __restrict__ outH, float* __restrict__ outLoc, float* __restrict__ outScore,
    int N, int Kp, int mode)
{
    extern __shared__ __align__(16) char smem[];
    const int m0 = blockIdx.y * 128;
    const int n0 = blockIdx.x * 128;
    const int nit = Kp / 32;

    const int tid = threadIdx.x, lane = tid & 31, wid = tid >> 5;
    const int wm = (wid >> 2) * 64, wn = (wid & 3) * 32;
    const int lg = lane >> 2, lt = lane & 3;
    const uint32_t sb = smem_u32(smem);

    const int lrow = tid >> 1, lseg = tid & 1;
    const __half* aBase = A + (size_t)(m0 + lrow) * Kp + lseg * 16;
    const __half* bBase = B + (size_t)(n0 + lrow) * Kp + lseg * 16;
    const uint32_t ldst = (uint32_t)(lrow * APITCH + lseg * 32);

    const uint32_t aLane = (uint32_t)((wm + (lane & 7) + ((lane >> 3) & 1) * 8) * APITCH + ((lane >> 4) & 1) * 16);
    const uint32_t bLane = (uint32_t)(128 * APITCH + (wn + (lane & 7) + ((lane >> 4) & 1) * 8) * APITCH + ((lane >> 3) & 1) * 16);

    float acc[4][4][4];
#pragma unroll
    for (int mi = 0; mi < 4; mi++)
#pragma unroll
        for (int ni = 0; ni < 4; ni++)
#pragma unroll
            for (int q = 0; q < 4; q++) acc[mi][ni][q] = 0.f;

    auto issue = [&](int g) {
        const uint32_t buf = sb + (g % 3) * GBUF;
        const __half* aS = aBase + g * 32;
        const __half* bS = bBase + g * 32;
        cp16(buf + ldst, aS); cp16(buf + ldst + 16, aS + 8);
        cp16(buf + 128 * APITCH + ldst, bS); cp16(buf + 128 * APITCH + ldst + 16, bS + 8);
        cp_commit();
    };

    issue(0);
    if (nit > 1) issue(1);

    for (int g = 0; g < nit; ++g) {
        if (g + 2 < nit) issue(g + 2);
        else cp_commit();
        cp_wait<2>();
        __syncthreads();

        const uint32_t buf = sb + (g % 3) * GBUF;
#pragma unroll
        for (int ks = 0; ks < 2; ks++) {
            uint32_t af[4][4], bf[4][2];
#pragma unroll
            for (int mi = 0; mi < 4; mi++)
                ldsm4(af[mi], buf + aLane + mi * (16 * APITCH) + ks * 32);
#pragma unroll
            for (int pr = 0; pr < 2; pr++) {
                uint32_t r[4];
                ldsm4(r, buf + bLane + pr * (16 * APITCH) + ks * 32);
                bf[pr * 2][0] = r[0]; bf[pr * 2][1] = r[1];
                bf[pr * 2 + 1][0] = r[2]; bf[pr * 2 + 1][1] = r[3];
            }
#pragma unroll
            for (int mi = 0; mi < 4; mi++)
#pragma unroll
                for (int ni = 0; ni < 4; ni++)
                    mma16(acc[mi][ni], af[mi], bf[ni]);
        }
        __syncthreads();
    }

#pragma unroll
    for (int mi = 0; mi < 4; mi++) {
        const int r0 = m0 + wm + mi * 16 + lg;
#pragma unroll
        for (int ni = 0; ni < 4; ni++) {
            const int cc = n0 + wn + ni * 8 + 2 * lt;
#pragma unroll
            for (int half_ = 0; half_ < 2; half_++) {
                const int rr = r0 + half_ * 8;
                const float v0 = acc[mi][ni][half_ * 2 + 0] + bias[cc];
                const float v1 = acc[mi][ni][half_ * 2 + 1] + bias[cc + 1];
                if (mode == 0) {
                    outH[(size_t)rr * N + cc]     = __float2half(fmaxf(v0, 0.f));
                    outH[(size_t)rr * N + cc + 1] = __float2half(fmaxf(v1, 0.f));
                } else {
                    if (cc < 324) outLoc[(size_t)rr * 324 + cc] = v0;
                    else if (cc < 405) outScore[(size_t)rr * 81 + cc - 324] = v0;
                    if (cc + 1 < 324) outLoc[(size_t)rr * 324 + cc + 1] = v1;
                    else if (cc + 1 < 405) outScore[(size_t)rr * 81 + cc + 1 - 324] = v1;
                }
            }
        }
    }
}

// ---------------- combine1 ----------------
__global__ __launch_bounds__(256) void combine1(const float* __restrict__ p1,
                                                const float* __restrict__ b0, const float* __restrict__ b1,
                                                __half2* __restrict__ TP0, __half2* __restrict__ TP1)
{
    __shared__ float s[64][65];
    const int b = blockIdx.z;
    const int m0 = blockIdx.x * 64, e0 = blockIdx.y * 64;
    const int tid = threadIdx.x;
    const float* src = p1 + (size_t)b * S1 * OCPAD1 * HW;
    const int r = tid >> 2, q0 = (tid & 3) * 16;
#pragma unroll
    for (int q = 0; q < 16; q++) {
        const int e = e0 + q0 + q;
        float v = 0.f;
        if (e < HW) {
#pragma unroll
            for (int ss = 0; ss < S1; ss++)
                v += src[((size_t)ss * OCPAD1 + m0 + r) * HW + e];
        }
        s[r][q0 + q] = v;
    }
    __syncthreads();
    const float* bias = b ? b1 : b0;
    __half2* TP = b ? TP1 : TP0;
#pragma unroll
    for (int k = 0; k < 8; k++) {
        const int widx = tid + k * 256;
        const int pl = widx >> 5, cp = widx & 31;
        const int e = e0 + pl;
        if (e < HW) {
            int row;
            if (b == 0) { const int i = e % 38, j = e / 38; row = (i + 7) * 64 + j + 7; }
            else        { const int i = e / 50, j = e % 50; row = (j + 7) * 64 + i + 7; }
            const float vx = s[2 * cp][pl] + bias[m0 + 2 * cp];
            const float vy = s[2 * cp + 1][pl] + bias[m0 + 2 * cp + 1];
            TP[(size_t)row * 128 + (m0 >> 1) + cp] = __floats2half2_rn(vx, vy);
        }
    }
}

// ---------------- combine2: h[p][512] position-major ----------------
__global__ void combine2(const float* __restrict__ h0, const float* __restrict__ h1,
                         const float* __restrict__ bc, const float* __restrict__ brr,
                         float* __restrict__ h)
{
    const int idx = blockIdx.x * blockDim.x + threadIdx.x;
    if (idx >= OUTDIM * HW) return;
    const int ch = idx / HW, p = idx - ch * HW;
    const int e = (p % 50) * 38 + p / 50;
    float v = bc[ch] + brr[ch];
#pragma unroll
    for (int ss = 0; ss < S2; ss++) {
        v += h0[((size_t)ss * OCPAD2 + ch) * HW + p];
        v += h1[((size_t)ss * OCPAD2 + ch) * HW + e];
    }
    h[(size_t)p * 512 + ch] = fmaxf(v, 0.f);
}

// ---------------- ROI bilinear max pool ----------------
__global__ void roi_pool(const float* __restrict__ h, const float* __restrict__ rois,
                         __half* __restrict__ flath)
{
    const int idx = blockIdx.x * blockDim.x + threadIdx.x;
    if (idx >= NROIS * OUTDIM) return;
    const int n  = idx / OUTDIM;
    const int ch = idx - n * OUTDIM;
    const int bin = ch / 10;
    const int bi  = bin / 7;
    const int bj  = bin - bi * 7;

    const float4 r = ((const float4*)rois)[n];
    const float xmin = (r.x * 0.0625f) / 50.f;
    const float ymin = (r.y * 0.0625f) / 38.f;
    const float xmax = (r.z * 0.0625f) / 50.f;
    const float ymax = (r.w * 0.0625f) / 38.f;
    const float stx = (xmax - xmin) / 7.f;
    const float sty = (ymax - ymin) / 7.f;

    float best = -3.4e38f;
#pragma unroll
    for (int ky = 0; ky < 2; ky++) {
        const float yy = (ymin + (float)(bi + ky) * sty) * 37.f;
        const float fy = floorf(yy);
        const float wy = yy - fy;
        const int y0 = (int)fminf(fmaxf(fy, 0.f), 37.f);
        const int y1 = (int)fminf(fmaxf(fy + 1.f, 0.f), 37.f);
#pragma unroll
        for (int kx = 0; kx < 2; kx++) {
            const float xx = (xmin + (float)(bj + kx) * stx) * 49.f;
            const float fx = floorf(xx);
            const float wx = xx - fx;
            const int x0 = (int)fminf(fmaxf(fx, 0.f), 49.f);
            const int x1 = (int)fminf(fmaxf(fx + 1.f, 0.f), 49.f);
            const float v00 = h[(size_t)(y0 * FW + x0) * 512 + ch];
            const float v01 = h[(size_t)(y0 * FW + x1) * 512 + ch];
            const float v10 = h[(size_t)(y1 * FW + x0) * 512 + ch];
            const float v11 = h[(size_t)(y1 * FW + x1) * 512 + ch];
            const float top = v00 + (v01 - v00) * wx;
            const float bot = v10 + (v11 - v10) * wx;
            const float val = top + (bot - top) * wy;
            best = fmaxf(best, val);
        }
    }
    flath[(size_t)n * 512 + ch] = __float2half(best);
}

// ---------------- launch ----------------
extern "C" void kernel_launch(void* const* d_in, const int* in_sizes, int n_in,
                              void* d_out, int out_size)
{
    const float* x          = (const float*)d_in[0];
    const float* rois       = (const float*)d_in[1];
    const float* w_col_max  = (const float*)d_in[2];
    const float* b_col_max  = (const float*)d_in[3];
    const float* w_col      = (const float*)d_in[4];
    const float* b_col      = (const float*)d_in[5];
    const float* w_row_max  = (const float*)d_in[6];
    const float* b_row_max  = (const float*)d_in[7];
    const float* w_row      = (const float*)d_in[8];
    const float* b_row      = (const float*)d_in[9];
    const float* w_fc1      = (const float*)d_in[10];
    const float* b_fc1      = (const float*)d_in[11];
    const float* w_score    = (const float*)d_in[12];
    const float* b_score    = (const float*)d_in[13];
    const float* w_loc      = (const float*)d_in[14];
    const float* b_loc      = (const float*)d_in[15];
    float* out = (float*)d_out;

    __half *XPa, *XPb, *TP0, *TP1, *wt1, *wt2, *flath, *fc1h, *wfc1h, *whh;
    float *p1, *h0, *h1, *h, *hbias;
    cudaGetSymbolAddress((void**)&XPa,   g_XPa);
    cudaGetSymbolAddress((void**)&XPb,   g_XPb);
    cudaGetSymbolAddress((void**)&TP0,   g_TP0);
    cudaGetSymbolAddress((void**)&TP1,   g_TP1);
    cudaGetSymbolAddress((void**)&wt1,   g_wt1);
    cudaGetSymbolAddress((void**)&wt2,   g_wt2);
    cudaGetSymbolAddress((void**)&p1,    g_p1);
    cudaGetSymbolAddress((void**)&h0,    g_h0);
    cudaGetSymbolAddress((void**)&h1,    g_h1);
    cudaGetSymbolAddress((void**)&h,     g_h);
    cudaGetSymbolAddress((void**)&flath, g_flath);
    cudaGetSymbolAddress((void**)&fc1h,  g_fc1h);
    cudaGetSymbolAddress((void**)&wfc1h, g_wfc1h);
    cudaGetSymbolAddress((void**)&whh,   g_whh);
    cudaGetSymbolAddress((void**)&hbias, g_hbias);

    cudaFuncSetAttribute(conv_mma, cudaFuncAttributeMaxDynamicSharedMemorySize, CONV_SMEM);
    cudaFuncSetAttribute(gemm_hmma, cudaFuncAttributeMaxDynamicSharedMemorySize, GEMM_SMEM);

    // NOTE: no zero_fill. Device globals are zero-initialized at module load and the
    // pad regions of XPa/XPb/TP0/TP1/flath are never written by any kernel, so they
    // remain zero across every call — identical behavior each launch.

    // #0: transpose x
    xpose<<<dim3(2048 / 64, (HW + 63) / 64), 256>>>(x, (__half2*)XPa, (__half2*)XPb);
    // #1: conv1 weights (both branches)
    wtrans<<<dim3(OCPAD1, 2048 / 128, 2), 256>>>(w_col_max, w_row_max, wt1,
        (size_t)TAPS * OCPAD1 * 2048, 256, OCPAD1, 2048);
    // #2: FC weight conversions
    cvt_fc<<<(2048 * 512 + 255) / 256, 256>>>(w_fc1, w_loc, w_score, b_loc, b_score,
                                              wfc1h, whh, hbias);
    // #3: conv1 (profiled index) — 15 x 2 x 10 = 300 CTAs, uneven 5-way K split
    {
        dim3 grid((HW + 127) / 128, OCPAD1 / 128, 2 * S1);
        conv_mma<<<grid, 256, CONV_SMEM>>>(
            XPb, XPa,
            wt1, wt1 + (size_t)TAPS * OCPAD1 * 2048,
            p1, p1 + (size_t)S1 * OCPAD1 * HW,
            38, 50, 2048, 64, OCPAD1, S1);
    }
    // #4: conv2 weights
    wtrans<<<dim3(OCPAD2, 256 / 128, 2), 256>>>(w_col, w_row, wt2,
        (size_t)TAPS * OCPAD2 * 256, OUTDIM, OCPAD2, 256);
    // #5: combine1
    combine1<<<dim3(OCPAD1 / 64, (HW + 63) / 64, 2), 256>>>(p1, b_col_max, b_row_max,
                                                            (__half2*)TP0, (__half2*)TP1);
    // #6: conv2 — 15 x 4 x 4 = 240 CTAs
    {
        dim3 grid((HW + 127) / 128, OCPAD2 / 128, 2 * S2);
        conv_mma<<<grid, 256, CONV_SMEM>>>(
            TP0, TP1,
            wt2, wt2 + (size_t)TAPS * OCPAD2 * 256,
            h0, h1,
            50, 38, 256, 8, OCPAD2, S2);
    }
    // #7: combine2 -> h [p][512]
    {
        const int n = OUTDIM * HW;
        combine2<<<(n + 255) / 256, 256>>>(h0, h1, b_col, b_row, h);
    }
    // #8: ROI pool -> flath
    {
        const int n = NROIS * OUTDIM;
        roi_pool<<<(n + 255) / 256, 256>>>(h, rois, flath);
    }
    // #9: fc1
    {
        dim3 grid(2048 / 128, NROIS / 128);
        gemm_hmma<<<grid, 256, GEMM_SMEM>>>(flath, wfc1h, b_fc1,
                                            fc1h, nullptr, nullptr, 2048, 512, 0);
    }
    // #10: heads
    {
        dim3 grid(512 / 128, NROIS / 128);
        gemm_hmma<<<grid, 256, GEMM_SMEM>>>(fc1h, whh, hbias,
                                            nullptr, out, out + NROIS * 324, 512, 2048, 1);
    }
}

// round 16
// speedup vs baseline: 1.6826x; 1.6826x over previous
#include <cuda_runtime.h>
#include <cuda_fp16.h>
#include <cstdint>
#include <cstring>

#define FH 38
#define FW 50
#define HW 1900
#define TAPS 15
#define NROIS 512
#define OUTDIM 490
#define S1 5
#define S2 2
#define SH 4                 // heads gemm K-split
#define OCPAD1 256
#define OCPAD2 512
#define PROWS 4096

// ---------------- scratch (zero-initialized at load; pads never written) ----------------
__device__ __half g_XPa[PROWS * 2048];
__device__ __half g_XPb[PROWS * 2048];
__device__ __half g_TP0[PROWS * 256];
__device__ __half g_TP1[PROWS * 256];
__device__ __half g_wt1[2 * TAPS * OCPAD1 * 2048];
__device__ __half g_wt2[2 * TAPS * OCPAD2 * 256];
__device__ float  g_p1[2 * S1 * OCPAD1 * HW];
__device__ float  g_h0[S2 * OCPAD2 * HW];
__device__ float  g_h1[S2 * OCPAD2 * HW];
__device__ float  g_h [HW * 512];
__device__ __half g_flath[NROIS * 512];
__device__ __half g_fc1h [NROIS * 2048];
__device__ __half g_wfc1h[2048 * 512];
__device__ __half g_whh  [512 * 2048];
__device__ float  g_hbias[512];
__device__ float  g_hp[SH * NROIS * 512];    // heads partials

// ---------------- PTX helpers ----------------
__device__ __forceinline__ uint32_t smem_u32(const void* p) {
    uint32_t a;
    asm("{ .reg .u64 t; cvta.to.shared.u64 t, %1; cvt.u32.u64 %0, t; }" : "=r"(a) : "l"(p));
    return a;
}
__device__ __forceinline__ void cp16(uint32_t dst, const __half* src) {
    asm volatile("cp.async.cg.shared.global [%0], [%1], 16;"
                 :: "r"(dst), "l"(__cvta_generic_to_global(src)));
}
__device__ __forceinline__ void cp_commit() { asm volatile("cp.async.commit_group;" ::: "memory"); }
template<int N> __device__ __forceinline__ void cp_wait() {
    asm volatile("cp.async.wait_group %0;" :: "n"(N) : "memory");
}
__device__ __forceinline__ void ldsm4(uint32_t* r, uint32_t addr) {
    asm volatile("ldmatrix.sync.aligned.m8n8.x4.shared.b16 {%0,%1,%2,%3}, [%4];"
        : "=r"(r[0]), "=r"(r[1]), "=r"(r[2]), "=r"(r[3]) : "r"(addr));
}
__device__ __forceinline__ void mma16(float* c, const uint32_t* a, const uint32_t* b) {
    asm volatile("mma.sync.aligned.m16n8k16.row.col.f32.f16.f16.f32 "
        "{%0,%1,%2,%3}, {%4,%5,%6,%7}, {%8,%9}, {%0,%1,%2,%3};"
        : "+f"(c[0]), "+f"(c[1]), "+f"(c[2]), "+f"(c[3])
        : "r"(a[0]), "r"(a[1]), "r"(a[2]), "r"(a[3]), "r"(b[0]), "r"(b[1]));
}

// ---------------- prep ----------------
__global__ __launch_bounds__(256) void xpose(const float* __restrict__ x,
                                             __half2* __restrict__ XPa, __half2* __restrict__ XPb)
{
    __shared__ float s[64][65];
    const int c0 = blockIdx.x * 64, p0 = blockIdx.y * 64;
    const int tid = threadIdx.x;
    const int r = tid >> 2, q0 = (tid & 3) * 16;
#pragma unroll
    for (int q = 0; q < 16; q++) {
        const int p = p0 + q0 + q;
        s[r][q0 + q] = (p < HW) ? x[(size_t)(c0 + r) * HW + p] : 0.f;
    }
    __syncthreads();
#pragma unroll
    for (int k = 0; k < 8; k++) {
        const int widx = tid + k * 256;
        const int pl = widx >> 5, cp = widx & 31;
        const int p = p0 + pl;
        if (p < HW) {
            const int i = p / FW, j = p - i * FW;
            const __half2 v = __floats2half2_rn(s[2 * cp][pl], s[2 * cp + 1][pl]);
            XPa[(size_t)((i + 7) * 64 + j + 7) * 1024 + (c0 >> 1) + cp] = v;
            XPb[(size_t)((j + 7) * 64 + i + 7) * 1024 + (c0 >> 1) + cp] = v;
        }
    }
}

// w [oc][ic][15] f32 -> wt [t][ocpad][ic] half; vectorized (16B stores)
__global__ __launch_bounds__(256) void wtrans(const float* __restrict__ w0, const float* __restrict__ w1,
                                              __half* __restrict__ wt, size_t dstStride,
                                              int OC, int OCpad, int IC)
{
    __shared__ __align__(16) float s[128 * TAPS];
    const float* w = blockIdx.z ? w1 : w0;
    __half* dst = wt + (size_t)blockIdx.z * dstStride;
    const int m = blockIdx.x, c0 = blockIdx.y * 128;
    const int tid = threadIdx.x;
    if (m < OC) {
        const float4* src4 = (const float4*)(w + ((size_t)m * IC + c0) * TAPS);
        for (int i = tid; i < 128 * TAPS / 4; i += 256) ((float4*)s)[i] = src4[i];
    } else {
        for (int i = tid; i < 128 * TAPS / 4; i += 256)
            ((float4*)s)[i] = make_float4(0.f, 0.f, 0.f, 0.f);
    }
    __syncthreads();
    if (tid < 240) {
        const int t = tid / 16, c8 = (tid & 15) * 8;
        __half2 hv[4];
#pragma unroll
        for (int k = 0; k < 4; k++)
            hv[k] = __floats2half2_rn(s[(c8 + 2 * k) * TAPS + t], s[(c8 + 2 * k + 1) * TAPS + t]);
        *(uint4*)&dst[((size_t)t * OCpad + m) * IC + c0 + c8] = *(uint4*)hv;
    }
}

__global__ void cvt_fc(const float* __restrict__ wfc1,
                       const float* __restrict__ wloc, const float* __restrict__ wsc,
                       const float* __restrict__ bloc, const float* __restrict__ bsc,
                       __half* __restrict__ wfc1h, __half* __restrict__ whh, float* __restrict__ hb)
{
    const int idx = blockIdx.x * blockDim.x + threadIdx.x;
    if (idx < 2048 * 512) {
        const int r = idx >> 9, c = idx & 511;
        wfc1h[idx] = __float2half(c < OUTDIM ? wfc1[(size_t)r * OUTDIM + c] : 0.f);
    }
    if (idx < 512 * 2048) {
        const int r = idx >> 11, k = idx & 2047;
        float v = 0.f;
        if (r < 324) v = wloc[(size_t)r * 2048 + k];
        else if (r < 405) v = wsc[(size_t)(r - 324) * 2048 + k];
        whh[idx] = __float2half(v);
    }
    if (idx < 512) {
        float v = 0.f;
        if (idx < 324) v = bloc[idx];
        else if (idx < 405) v = bsc[idx - 324];
        hb[idx] = v;
    }
}

// ============ sliding-window tap conv: BN=128, 2 CTAs/SM, uneven K-split ============
#define WR 320
#define APITCH 80
#define ABUF (128 * APITCH)
#define BBUF (WR * APITCH)
#define CONV_SMEM (4 * ABUF + 2 * BBUF)    // 92160

__global__ __launch_bounds__(256, 2) void conv_mma(
    const __half* __restrict__ inB0, const __half* __restrict__ inB1,
    const __half* __restrict__ wA0,  const __half* __restrict__ wA1,
    float* __restrict__ out0, float* __restrict__ out1,
    int D0, int D1, int ICfull, int CT, int OCpad, int S)
{
    extern __shared__ __align__(16) char smem[];
    const int z = blockIdx.z;
    const int br = z / S, s = z % S;
    const __half* inB = br ? inB1 : inB0;
    const __half* wA  = br ? wA1  : wA0;
    const int D = br ? D1 : D0;
    float* out = (br ? out1 : out0) + (size_t)s * OCpad * HW;
    const int m0 = blockIdx.y * 128;
    const int pi0 = blockIdx.x * 128;
    const int cs = (s * CT) / S, ce = ((s + 1) * CT) / S;
    const int icChunks = ce - cs;
    const int icOff = cs * 32;
    const int nit = icChunks * TAPS;
    const int row0 = (pi0 / D + 7) * 64 + pi0 % D;

    const int tid = threadIdx.x, lane = tid & 31, wid = tid >> 5;
    const int wm = (wid >> 2) * 64;
    const int wn = (wid & 3) * 32;
    const int lg = lane >> 2, lt = lane & 3;
    const uint32_t sb = smem_u32(smem);
    const uint32_t aB[4] = { sb, sb + ABUF, sb + 2 * ABUF, sb + 3 * ABUF };
    const uint32_t bB[2] = { sb + 4 * ABUF, sb + 4 * ABUF + BBUF };

    const int arow = tid >> 1, aseg = tid & 1;
    const __half* aBase = wA + (size_t)(m0 + arow) * ICfull + icOff + aseg * 16;
    const size_t aTap = (size_t)OCpad * ICfull;
    const uint32_t aDst = (uint32_t)(arow * APITCH + aseg * 32);
    const uint32_t aLane = (uint32_t)((wm + (lane & 7) + ((lane >> 3) & 1) * 8) * APITCH + ((lane >> 4) & 1) * 16);

    uint32_t bLaneOff[2];
#pragma unroll
    for (int pr = 0; pr < 2; pr++) {
        const int nl = wn + (lane & 7) + ((lane >> 4) & 1) * 8 + pr * 16;
        int pi = pi0 + nl; if (pi > HW - 1) pi = HW - 1;
        const int rr = (pi / D + 7) * 64 + pi % D + 7 - row0 - 7;
        bLaneOff[pr] = (uint32_t)(rr * APITCH + ((lane >> 3) & 1) * 16);
    }

    float acc[4][4][4];
#pragma unroll
    for (int mi = 0; mi < 4; mi++)
#pragma unroll
        for (int ni = 0; ni < 4; ni++)
#pragma unroll
            for (int q = 0; q < 4; q++) acc[mi][ni][q] = 0.f;

    auto issueA = [&](int g) {
        const int t = g % TAPS, c = g / TAPS;
        const __half* aS = aBase + (size_t)t * aTap + c * 32;
        const uint32_t d = aB[g & 3] + aDst;
        cp16(d, aS); cp16(d + 16, aS + 8);
    };
    auto issueBwin = [&](int c) {
        const uint32_t bb = bB[c & 1];
        for (int wr = tid; wr < WR; wr += 256) {
            int grow = row0 + wr; if (grow > PROWS - 1) grow = PROWS - 1;
            const __half* src = inB + (size_t)grow * ICfull + icOff + c * 32;
            const uint32_t d = bb + wr * APITCH;
            cp16(d, src); cp16(d + 16, src + 8); cp16(d + 32, src + 16); cp16(d + 48, src + 24);
        }
    };

    issueA(0); issueBwin(0); cp_commit();
    if (nit > 1) issueA(1);
    cp_commit();

    int tCur = 0, cCur = 0;
    for (int g = 0; g < nit; ++g) {
        const int gn = g + 2;
        if (gn < nit) {
            issueA(gn);
            if (gn % TAPS == 0) issueBwin(gn / TAPS);
        }
        cp_commit();
        cp_wait<2>();
        __syncthreads();

        const uint32_t abuf = aB[g & 3];
        const uint32_t bbuf = bB[cCur & 1] + tCur * APITCH;
#pragma unroll
        for (int ks = 0; ks < 2; ks++) {
            uint32_t af[4][4], bf[4][2];
#pragma unroll
            for (int mi = 0; mi < 4; mi++)
                ldsm4(af[mi], abuf + aLane + mi * (16 * APITCH) + ks * 32);
#pragma unroll
            for (int pr = 0; pr < 2; pr++) {
                uint32_t r[4];
                ldsm4(r, bbuf + bLaneOff[pr] + ks * 32);
                bf[pr * 2][0] = r[0]; bf[pr * 2][1] = r[1];
                bf[pr * 2 + 1][0] = r[2]; bf[pr * 2 + 1][1] = r[3];
            }
#pragma unroll
            for (int mi = 0; mi < 4; mi++)
#pragma unroll
                for (int ni = 0; ni < 4; ni++)
                    mma16(acc[mi][ni], af[mi], bf[ni]);
        }
        if (++tCur == TAPS) { tCur = 0; cCur++; }
    }

#pragma unroll
    for (int mi = 0; mi < 4; mi++) {
        const int r0 = m0 + wm + mi * 16 + lg;
#pragma unroll
        for (int ni = 0; ni < 4; ni++) {
            const int cc = pi0 + wn + ni * 8 + 2 * lt;
            if (cc < HW) {
                *(float2*)&out[(size_t)r0 * HW + cc] = make_float2(acc[mi][ni][0], acc[mi][ni][1]);
                *(float2*)&out[(size_t)(r0 + 8) * HW + cc] = make_float2(acc[mi][ni][2], acc[mi][ni][3]);
            }
        }
    }
}

// ============ fp16 GEMM for FC ============
// mode 0: outH[m*N+n] = half(relu(acc + bias[n]))      (gridDim.z = 1)
// mode 1: partial float acc -> outP[z][m][512]          (gridDim.z = SH, no bias)
#define GBUF (2 * 128 * APITCH)
#define GEMM_SMEM (3 * GBUF)

__global__ __launch_bounds__(256) void gemm_hmma(
    const __half* __restrict__ A, const __half* __restrict__ B, const float* __restrict__ bias,
    __half* __restrict__ outH, float* __restrict__ outP,
    int N, int ldk, int Kp, int mode)
{
    extern __shared__ __align__(16) char smem[];
    const int m0 = blockIdx.y * 128;
    const int n0 = blockIdx.x * 128;
    const int z  = blockIdx.z;
    const int kOff = z * Kp;
    const int nit = Kp / 32;

    const int tid = threadIdx.x, lane = tid & 31, wid = tid >> 5;
    const int wm = (wid >> 2) * 64, wn = (wid & 3) * 32;
    const int lg = lane >> 2, lt = lane & 3;
    const uint32_t sb = smem_u32(smem);

    const int lrow = tid >> 1, lseg = tid & 1;
    const __half* aBase = A + (size_t)(m0 + lrow) * ldk + kOff + lseg * 16;
    const __half* bBase = B + (size_t)(n0 + lrow) * ldk + kOff + lseg * 16;
    const uint32_t ldst = (uint32_t)(lrow * APITCH + lseg * 32);

    const uint32_t aLane = (uint32_t)((wm + (lane & 7) + ((lane >> 3) & 1) * 8) * APITCH + ((lane >> 4) & 1) * 16);
    const uint32_t bLane = (uint32_t)(128 * APITCH + (wn + (lane & 7) + ((lane >> 4) & 1) * 8) * APITCH + ((lane >> 3) & 1) * 16);

    float acc[4][4][4];
#pragma unroll
    for (int mi = 0; mi < 4; mi++)
#pragma unroll
        for (int ni = 0; ni < 4; ni++)
#pragma unroll
            for (int q = 0; q < 4; q++) acc[mi][ni][q] = 0.f;

    auto issue = [&](int g) {
        const uint32_t buf = sb + (g % 3) * GBUF;
        const __half* aS = aBase + g * 32;
        const __half* bS = bBase + g * 32;
        cp16(buf + ldst, aS); cp16(buf + ldst + 16, aS + 8);
        cp16(buf + 128 * APITCH + ldst, bS); cp16(buf + 128 * APITCH + ldst + 16, bS + 8);
        cp_commit();
    };

    issue(0);
    if (nit > 1) issue(1);

    for (int g = 0; g < nit; ++g) {
        if (g + 2 < nit) issue(g + 2);
        else cp_commit();
        cp_wait<2>();
        __syncthreads();

        const uint32_t buf = sb + (g % 3) * GBUF;
#pragma unroll
        for (int ks = 0; ks < 2; ks++) {
            uint32_t af[4][4], bf[4][2];
#pragma unroll
            for (int mi = 0; mi < 4; mi++)
                ldsm4(af[mi], buf + aLane + mi * (16 * APITCH) + ks * 32);
#pragma unroll
            for (int pr = 0; pr < 2; pr++) {
                uint32_t r[4];
                ldsm4(r, buf + bLane + pr * (16 * APITCH) + ks * 32);
                bf[pr * 2][0] = r[0]; bf[pr * 2][1] = r[1];
                bf[pr * 2 + 1][0] = r[2]; bf[pr * 2 + 1][1] = r[3];
            }
#pragma unroll
            for (int mi = 0; mi < 4; mi++)
#pragma unroll
                for (int ni = 0; ni < 4; ni++)
                    mma16(acc[mi][ni], af[mi], bf[ni]);
        }
        __syncthreads();
    }

#pragma unroll
    for (int mi = 0; mi < 4; mi++) {
        const int r0 = m0 + wm + mi * 16 + lg;
#pragma unroll
        for (int ni = 0; ni < 4; ni++) {
            const int cc = n0 + wn + ni * 8 + 2 * lt;
#pragma unroll
            for (int hf = 0; hf < 2; hf++) {
                const int rr = r0 + hf * 8;
                if (mode == 0) {
                    const float v0 = acc[mi][ni][hf * 2 + 0] + bias[cc];
                    const float v1 = acc[mi][ni][hf * 2 + 1] + bias[cc + 1];
                    outH[(size_t)rr * N + cc]     = __float2half(fmaxf(v0, 0.f));
                    outH[(size_t)rr * N + cc + 1] = __float2half(fmaxf(v1, 0.f));
                } else {
                    *(float2*)&outP[((size_t)z * NROIS + rr) * 512 + cc] =
                        make_float2(acc[mi][ni][hf * 2 + 0], acc[mi][ni][hf * 2 + 1]);
                }
            }
        }
    }
}

// ---------------- reduce heads partials (fixed order -> deterministic) ----------------
__global__ void reduce_heads(const float* __restrict__ hp, const float* __restrict__ hb,
                             float* __restrict__ outLoc, float* __restrict__ outScore)
{
    const int idx = blockIdx.x * blockDim.x + threadIdx.x;
    if (idx >= NROIS * 512) return;
    const int m = idx >> 9, n = idx & 511;
    if (n >= 405) return;
    float v = hb[n];
#pragma unroll
    for (int z = 0; z < SH; z++) v += hp[(size_t)z * NROIS * 512 + idx];
    if (n < 324) outLoc[(size_t)m * 324 + n] = v;
    else outScore[(size_t)m * 81 + n - 324] = v;
}

// ---------------- combine1 ----------------
__global__ __launch_bounds__(256) void combine1(const float* __restrict__ p1,
                                                const float* __restrict__ b0, const float* __restrict__ b1,
                                                __half2* __restrict__ TP0, __half2* __restrict__ TP1)
{
    __shared__ float s[64][65];
    const int b = blockIdx.z;
    const int m0 = blockIdx.x * 64, e0 = blockIdx.y * 64;
    const int tid = threadIdx.x;
    const float* src = p1 + (size_t)b * S1 * OCPAD1 * HW;
    const int r = tid >> 2, q0 = (tid & 3) * 16;
#pragma unroll
    for (int q = 0; q < 16; q++) {
        const int e = e0 + q0 + q;
        float v = 0.f;
        if (e < HW) {
#pragma unroll
            for (int ss = 0; ss < S1; ss++)
                v += src[((size_t)ss * OCPAD1 + m0 + r) * HW + e];
        }
        s[r][q0 + q] = v;
    }
    __syncthreads();
    const float* bias = b ? b1 : b0;
    __half2* TP = b ? TP1 : TP0;
#pragma unroll
    for (int k = 0; k < 8; k++) {
        const int widx = tid + k * 256;
        const int pl = widx >> 5, cp = widx & 31;
        const int e = e0 + pl;
        if (e < HW) {
            int row;
            if (b == 0) { const int i = e % 38, j = e / 38; row = (i + 7) * 64 + j + 7; }
            else        { const int i = e / 50, j = e % 50; row = (j + 7) * 64 + i + 7; }
            const float vx = s[2 * cp][pl] + bias[m0 + 2 * cp];
            const float vy = s[2 * cp + 1][pl] + bias[m0 + 2 * cp + 1];
            TP[(size_t)row * 128 + (m0 >> 1) + cp] = __floats2half2_rn(vx, vy);
        }
    }
}

// ---------------- combine2: h[p][512] position-major ----------------
__global__ void combine2(const float* __restrict__ h0, const float* __restrict__ h1,
                         const float* __restrict__ bc, const float* __restrict__ brr,
                         float* __restrict__ h)
{
    const int idx = blockIdx.x * blockDim.x + threadIdx.x;
    if (idx >= OUTDIM * HW) return;
    const int ch = idx / HW, p = idx - ch * HW;
    const int e = (p % 50) * 38 + p / 50;
    float v = bc[ch] + brr[ch];
#pragma unroll
    for (int ss = 0; ss < S2; ss++) {
        v += h0[((size_t)ss * OCPAD2 + ch) * HW + p];
        v += h1[((size_t)ss * OCPAD2 + ch) * HW + e];
    }
    h[(size_t)p * 512 + ch] = fmaxf(v, 0.f);
}

// ---------------- ROI bilinear max pool ----------------
__global__ void roi_pool(const float* __restrict__ h, const float* __restrict__ rois,
                         __half* __restrict__ flath)
{
    const int idx = blockIdx.x * blockDim.x + threadIdx.x;
    if (idx >= NROIS * OUTDIM) return;
    const int n  = idx / OUTDIM;
    const int ch = idx - n * OUTDIM;
    const int bin = ch / 10;
    const int bi  = bin / 7;
    const int bj  = bin - bi * 7;

    const float4 r = ((const float4*)rois)[n];
    const float xmin = (r.x * 0.0625f) / 50.f;
    const float ymin = (r.y * 0.0625f) / 38.f;
    const float xmax = (r.z * 0.0625f) / 50.f;
    const float ymax = (r.w * 0.0625f) / 38.f;
    const float stx = (xmax - xmin) / 7.f;
    const float sty = (ymax - ymin) / 7.f;

    float best = -3.4e38f;
#pragma unroll
    for (int ky = 0; ky < 2; ky++) {
        const float yy = (ymin + (float)(bi + ky) * sty) * 37.f;
        const float fy = floorf(yy);
        const float wy = yy - fy;
        const int y0 = (int)fminf(fmaxf(fy, 0.f), 37.f);
        const int y1 = (int)fminf(fmaxf(fy + 1.f, 0.f), 37.f);
#pragma unroll
        for (int kx = 0; kx < 2; kx++) {
            const float xx = (xmin + (float)(bj + kx) * stx) * 49.f;
            const float fx = floorf(xx);
            const float wx = xx - fx;
            const int x0 = (int)fminf(fmaxf(fx, 0.f), 49.f);
            const int x1 = (int)fminf(fmaxf(fx + 1.f, 0.f), 49.f);
            const float v00 = h[(size_t)(y0 * FW + x0) * 512 + ch];
            const float v01 = h[(size_t)(y0 * FW + x1) * 512 + ch];
            const float v10 = h[(size_t)(y1 * FW + x0) * 512 + ch];
            const float v11 = h[(size_t)(y1 * FW + x1) * 512 + ch];
            const float top = v00 + (v01 - v00) * wx;
            const float bot = v10 + (v11 - v10) * wx;
            const float val = top + (bot - top) * wy;
            best = fmaxf(best, val);
        }
    }
    flath[(size_t)n * 512 + ch] = __float2half(best);
}

// ---------------- launch ----------------
extern "C" void kernel_launch(void* const* d_in, const int* in_sizes, int n_in,
                              void* d_out, int out_size)
{
    const float* x          = (const float*)d_in[0];
    const float* rois       = (const float*)d_in[1];
    const float* w_col_max  = (const float*)d_in[2];
    const float* b_col_max  = (const float*)d_in[3];
    const float* w_col      = (const float*)d_in[4];
    const float* b_col      = (const float*)d_in[5];
    const float* w_row_max  = (const float*)d_in[6];
    const float* b_row_max  = (const float*)d_in[7];
    const float* w_row      = (const float*)d_in[8];
    const float* b_row      = (const float*)d_in[9];
    const float* w_fc1      = (const float*)d_in[10];
    const float* b_fc1      = (const float*)d_in[11];
    const float* w_score    = (const float*)d_in[12];
    const float* b_score    = (const float*)d_in[13];
    const float* w_loc      = (const float*)d_in[14];
    const float* b_loc      = (const float*)d_in[15];
    float* out = (float*)d_out;

    __half *XPa, *XPb, *TP0, *TP1, *wt1, *wt2, *flath, *fc1h, *wfc1h, *whh;
    float *p1, *h0, *h1, *h, *hbias, *hp;
    cudaGetSymbolAddress((void**)&XPa,   g_XPa);
    cudaGetSymbolAddress((void**)&XPb,   g_XPb);
    cudaGetSymbolAddress((void**)&TP0,   g_TP0);
    cudaGetSymbolAddress((void**)&TP1,   g_TP1);
    cudaGetSymbolAddress((void**)&wt1,   g_wt1);
    cudaGetSymbolAddress((void**)&wt2,   g_wt2);
    cudaGetSymbolAddress((void**)&p1,    g_p1);
    cudaGetSymbolAddress((void**)&h0,    g_h0);
    cudaGetSymbolAddress((void**)&h1,    g_h1);
    cudaGetSymbolAddress((void**)&h,     g_h);
    cudaGetSymbolAddress((void**)&flath, g_flath);
    cudaGetSymbolAddress((void**)&fc1h,  g_fc1h);
    cudaGetSymbolAddress((void**)&wfc1h, g_wfc1h);
    cudaGetSymbolAddress((void**)&whh,   g_whh);
    cudaGetSymbolAddress((void**)&hbias, g_hbias);
    cudaGetSymbolAddress((void**)&hp,    g_hp);

    cudaFuncSetAttribute(conv_mma, cudaFuncAttributeMaxDynamicSharedMemorySize, CONV_SMEM);
    cudaFuncSetAttribute(gemm_hmma, cudaFuncAttributeMaxDynamicSharedMemorySize, GEMM_SMEM);

    // No zero_fill: device globals are zero-initialized at module load and the pad
    // regions of XPa/XPb/TP0/TP1/flath are never written by any kernel.

    // #0: transpose x
    xpose<<<dim3(2048 / 64, (HW + 63) / 64), 256>>>(x, (__half2*)XPa, (__half2*)XPb);
    // #1: conv1 weights (both branches)
    wtrans<<<dim3(OCPAD1, 2048 / 128, 2), 256>>>(w_col_max, w_row_max, wt1,
        (size_t)TAPS * OCPAD1 * 2048, 256, OCPAD1, 2048);
    // #2: FC weight conversions
    cvt_fc<<<(2048 * 512 + 255) / 256, 256>>>(w_fc1, w_loc, w_score, b_loc, b_score,
                                              wfc1h, whh, hbias);
    // #3: conv1 (profiled index) — 300 CTAs, uneven 5-way K split
    {
        dim3 grid((HW + 127) / 128, OCPAD1 / 128, 2 * S1);
        conv_mma<<<grid, 256, CONV_SMEM>>>(
            XPb, XPa,
            wt1, wt1 + (size_t)TAPS * OCPAD1 * 2048,
            p1, p1 + (size_t)S1 * OCPAD1 * HW,
            38, 50, 2048, 64, OCPAD1, S1);
    }
    // #4: conv2 weights
    wtrans<<<dim3(OCPAD2, 256 / 128, 2), 256>>>(w_col, w_row, wt2,
        (size_t)TAPS * OCPAD2 * 256, OUTDIM, OCPAD2, 256);
    // #5: combine1
    combine1<<<dim3(OCPAD1 / 64, (HW + 63) / 64, 2), 256>>>(p1, b_col_max, b_row_max,
                                                            (__half2*)TP0, (__half2*)TP1);
    // #6: conv2 — 240 CTAs
    {
        dim3 grid((HW + 127) / 128, OCPAD2 / 128, 2 * S2);
        conv_mma<<<grid, 256, CONV_SMEM>>>(
            TP0, TP1,
            wt2, wt2 + (size_t)TAPS * OCPAD2 * 256,
            h0, h1,
            50, 38, 256, 8, OCPAD2, S2);
    }
    // #7: combine2 -> h [p][512]
    {
        const int n = OUTDIM * HW;
        combine2<<<(n + 255) / 256, 256>>>(h0, h1, b_col, b_row, h);
    }
    // #8: ROI pool -> flath
    {
        const int n = NROIS * OUTDIM;
        roi_pool<<<(n + 255) / 256, 256>>>(h, rois, flath);
    }
    // #9: fc1 = relu(flat @ w_fc1^T + b_fc1) -> fc1h half
    {
        dim3 grid(2048 / 128, NROIS / 128, 1);
        gemm_hmma<<<grid, 256, GEMM_SMEM>>>(flath, wfc1h, b_fc1,
                                            fc1h, nullptr, 2048, 512, 512, 0);
    }
    // #10: heads partials — K split 4 -> 64 CTAs
    {
        dim3 grid(512 / 128, NROIS / 128, SH);
        gemm_hmma<<<grid, 256, GEMM_SMEM>>>(fc1h, whh, nullptr,
                                            nullptr, hp, 512, 2048, 2048 / SH, 1);
    }
    // #11: reduce partials + bias -> out
    {
        const int n = NROIS * 512;
        reduce_heads<<<(n + 255) / 256, 256>>>(hp, hbias, out, out + NROIS * 324);
    }
}